// round 14
// baseline (speedup 1.0000x reference)
#include <cuda_runtime.h>

// TSM temporal shift: x (128, 96, 56, 56) f32, N_FRAME=8, fold=32.
//   c in [0,32):  out[b,t] = x[b,t+1]  (0 at t=7)
//   c in [32,64): out[b,t] = x[b,t-1]  (0 at t=0)
//   c in [64,96): copy
// R7: persistent/near-single-wave probe. 10752 tiles (each 896 float4,
// TPB=128 x V=7) processed by 1792 CTAs x exactly 6 tiles (grid-stride).
// Removes wave-transition overhead; inner body identical to the proven R5
// shape (block-uniform predication, front-batched LDG.128, ldcs/stcs).
// At ~7.2 TB/s delivered (289 MB irreducible) this is the last mechanism.

static constexpr int HW4     = (56 * 56) / 4;   // 784 float4 per channel plane
static constexpr int G4      = 32 * HW4;        // 25088 float4 per group per bt
static constexpr int PER_BT4 = 3 * G4;          // 75264 float4 per bt slice
static constexpr int V       = 7;               // float4 per thread
static constexpr int TPB     = 128;
static constexpr int XPG     = G4 / (V * TPB);  // 28 x-chunks per group
static constexpr int TILES   = 128 * 3 * XPG;   // 10752 tiles total
static constexpr int NCTA    = 1792;            // 10752 / 1792 = 6 tiles per CTA
static constexpr int ITERS   = TILES / NCTA;    // 6, exact

__global__ __launch_bounds__(TPB) void tsm_kernel(const float4* __restrict__ in,
                                                  float4* __restrict__ out) {
    #pragma unroll
    for (int it = 0; it < ITERS; it++) {
        const int tile = blockIdx.x + it * NCTA;

        // tile -> (bt, g, xb); per-CTA uniform (warp-uniform divides).
        const int bt = tile / (3 * XPG);
        const int gx = tile - bt * (3 * XPG);
        const int g  = gx / XPG;
        const int xb = gx - g * XPG;
        const int t  = bt & 7;          // frame within clip of 8

        const int  dt    = (g == 0) ? 1 : ((g == 1) ? -1 : 0);
        const bool valid = (g == 2) || ((g == 0) ? (t < 7) : (t > 0));

        const int chunk = g * G4 + xb * (V * TPB) + threadIdx.x;
        const float4* src = in  + (bt + dt) * PER_BT4 + chunk;
        float4*       dst = out + bt * PER_BT4 + chunk;

        float4 v[V];
        if (valid) {
            // Front-batched loads: 7 independent LDG.128 in flight per thread.
            #pragma unroll
            for (int k = 0; k < V; k++) v[k] = __ldcs(src + k * TPB);
        } else {
            #pragma unroll
            for (int k = 0; k < V; k++) v[k] = make_float4(0.f, 0.f, 0.f, 0.f);
        }

        #pragma unroll
        for (int k = 0; k < V; k++) __stcs(dst + k * TPB, v[k]);
    }
}

extern "C" void kernel_launch(void* const* d_in, const int* in_sizes, int n_in,
                              void* d_out, int out_size) {
    const float4* in  = (const float4*)d_in[0];
    float4*       out = (float4*)d_out;

    tsm_kernel<<<NCTA, TPB>>>(in, out);   // 1792 CTAs x 6 tiles, exact cover
}

// round 15
// speedup vs baseline: 1.1144x; 1.1144x over previous
#include <cuda_runtime.h>

// TSM temporal shift: x (128, 96, 56, 56) f32, N_FRAME=8, fold=32.
//   c in [0,32):  out[b,t] = x[b,t+1]  (0 at t=7)
//   c in [32,64): out[b,t] = x[b,t-1]  (0 at t=0)
//   c in [64,96): copy
// FINAL (revert to R5, the empirically best shape): block-uniform
// decomposition (group -> blockIdx.y, bt -> blockIdx.z), TPB=128, V=7
// (exact: 25088 = 28 * 128 * 7), front-batched LDG.128, ldcs/stcs
// streaming. Zero blocks (t=7/g=0, t=0/g=1) skip all loads.
//
// Roofline status: 289 MB irreducible traffic (138 MB read + 151 MB write)
// delivered in ~40.1 us = ~7.2 TB/s, ~90% of HBM spec. Seven structural
// variants (V, TPB, CTA count, grid mapping, R/W interleave, address-order
// sweep, persistent) all land 40.1-43.4 us; residual DRAM idle cycles are
// read/write bus-turnaround + refresh, not addressable from the SM side.

static constexpr int HW4     = (56 * 56) / 4;   // 784 float4 per channel plane
static constexpr int G4      = 32 * HW4;        // 25088 float4 per group per bt
static constexpr int PER_BT4 = 3 * G4;          // 75264 float4 per bt slice
static constexpr int V       = 7;               // float4 per thread
static constexpr int TPB     = 128;
static constexpr int BLK_X   = G4 / (V * TPB);  // 28, exact

__global__ __launch_bounds__(TPB) void tsm_kernel(const float4* __restrict__ in,
                                                  float4* __restrict__ out) {
    const int g  = blockIdx.y;       // channel group: 0 = t+1, 1 = t-1, 2 = copy
    const int bt = blockIdx.z;
    const int t  = bt & 7;           // frame within clip of 8

    // Block-uniform source shift and validity.
    const int  dt    = (g == 0) ? 1 : ((g == 1) ? -1 : 0);
    const bool valid = (g == 2) || ((g == 0) ? (t < 7) : (t > 0));

    const int chunk = g * G4 + blockIdx.x * (V * TPB) + threadIdx.x;
    const float4* src = in  + (bt + dt) * PER_BT4 + chunk;
    float4*       dst = out + bt * PER_BT4 + chunk;

    float4 v[V];
    if (valid) {
        // Front-batched loads: 7 independent LDG.128 in flight per thread.
        #pragma unroll
        for (int k = 0; k < V; k++) v[k] = __ldcs(src + k * TPB);
    } else {
        #pragma unroll
        for (int k = 0; k < V; k++) v[k] = make_float4(0.f, 0.f, 0.f, 0.f);
    }

    #pragma unroll
    for (int k = 0; k < V; k++) __stcs(dst + k * TPB, v[k]);
}

extern "C" void kernel_launch(void* const* d_in, const int* in_sizes, int n_in,
                              void* d_out, int out_size) {
    const float4* in  = (const float4*)d_in[0];
    float4*       out = (float4*)d_out;

    dim3 grid(BLK_X, 3, 128);   // (28, 3, 128) = 10752 blocks, exact cover
    tsm_kernel<<<grid, TPB>>>(in, out);
}